// round 7
// baseline (speedup 1.0000x reference)
#include <cuda_runtime.h>
#include <cuda_fp16.h>
#include <cstdint>

// Problem constants
static constexpr int Bc  = 2;
static constexpr int Lc  = 2048;
static constexpr int Dc  = 1024;
static constexpr int Hc  = 16;

// Scratch (__device__ globals: allocation-free rule)
__device__ __half g_qk  [(size_t)Bc * Lc * 2 * Dc];     // [4096][2048] q|k fp16
__device__ __half g_xh  [(size_t)Bc * Lc * Dc];         // x fp16
__device__ __half g_Wh  [(size_t)2 * Dc * Dc];          // W[:2048] fp16
__device__ __half g_xTh [(size_t)Bc * Dc * Lc];         // x^T fp16
__device__ __half g_atnH[(size_t)Bc * Lc * Lc];         // attn fp16 (K5 operand)
__device__ float  g_w   [(size_t)Bc * Lc * Lc];         // unnormalized weights fp32
__device__ float  g_part[(size_t)Bc * Hc * 16 * Lc];    // partial sums (reused)
__device__ float  g_gs  [Bc * Hc * Lc];                 // per (b,h,q) sumexp
__device__ float  g_rn  [Bc * Lc];                      // per (b,q) renorm sum
__device__ float  g_attn[(size_t)Bc * Lc * Lc];         // fallback attn buffer

// ---------------------------------------------------------------------------
__device__ __forceinline__ uint32_t smem_u32(const void* p) {
    uint32_t a;
    asm("{ .reg .u64 t; cvta.to.shared.u64 t, %1; cvt.u32.u64 %0, t; }" : "=r"(a) : "l"(p));
    return a;
}
__device__ __forceinline__ void mma16(float* c, const uint32_t* a, const uint32_t* b) {
    asm volatile(
        "mma.sync.aligned.m16n8k16.row.col.f32.f16.f16.f32 "
        "{%0,%1,%2,%3}, {%4,%5,%6,%7}, {%8,%9}, {%0,%1,%2,%3};"
        : "+f"(c[0]), "+f"(c[1]), "+f"(c[2]), "+f"(c[3])
        : "r"(a[0]), "r"(a[1]), "r"(a[2]), "r"(a[3]), "r"(b[0]), "r"(b[1]));
}
#define LDMX4(r0, r1, r2, r3, addr) \
    asm volatile("ldmatrix.sync.aligned.m8n8.x4.shared.b16 {%0,%1,%2,%3}, [%4];" \
        : "=r"(r0), "=r"(r1), "=r"(r2), "=r"(r3) : "r"(addr))
__device__ __forceinline__ void cp_async16(uint32_t dst, const void* src) {
    asm volatile("cp.async.cg.shared.global [%0], [%1], 16;" :: "r"(dst), "l"(src));
}
#define CP_COMMIT() asm volatile("cp.async.commit_group;" ::: "memory")
#define CP_WAIT(N)  asm volatile("cp.async.wait_group %0;" :: "n"(N) : "memory")

static constexpr int CHUNK = 64;
static constexpr int PADH  = 72;                        // 64 + 8 pad halves
static constexpr int AB_HALVES = 128 * PADH;            // 9216
static constexpr int STAGE_HALVES = 2 * AB_HALVES;      // A then B
static constexpr int NSTAGE = 3;
static constexpr int SMEM_GEMM_BYTES = NSTAGE * STAGE_HALVES * 2;   // 110592

// ---------------------------------------------------------------------------
// fp16 warp-MMA GEMM: C[128x128/blk] = f(alpha * A @ B^T)  (A,B K-major fp16)
// EPI: 0 = fp32 store, 1 = +bias -> fp16, 3 = exp(v-6) row-sum partials ONLY
// 256 thr = 8 warps (4m x 2n), warp tile 32x64, k-chunk 64, 3-stage ring.
// ---------------------------------------------------------------------------
template <int EPI, typename CT>
__global__ __launch_bounds__(256, 2)
void gemm_h(const __half* __restrict__ A, int lda, long aOut, long aIn,
            const __half* __restrict__ B, int ldb, long bOut, long bIn,
            CT* __restrict__ C, int ldc, long cOut, long cIn,
            int zInner, int Kd, float alpha,
            const float* __restrict__ bias, float* __restrict__ partial)
{
    extern __shared__ __align__(16) char smemc[];
    const uint32_t sb = smem_u32(smemc);

    const int tid  = threadIdx.x;
    const int wid  = tid >> 5;
    const int lane = tid & 31;
    const int wm   = wid >> 1;
    const int wn   = wid & 1;
    const int lq   = lane >> 2;
    const int lr   = lane & 3;

    const int z  = blockIdx.z;
    const int zo = z / zInner, zi = z % zInner;
    A += (long)zo * aOut + (long)zi * aIn;
    B += (long)zo * bOut + (long)zi * bIn;
    C += (long)zo * cOut + (long)zi * cIn;

    const int m0 = blockIdx.y * 128;
    const int n0 = blockIdx.x * 128;

    float acc[2][8][4];
#pragma unroll
    for (int mt = 0; mt < 2; mt++)
#pragma unroll
        for (int nt = 0; nt < 8; nt++)
#pragma unroll
            for (int i = 0; i < 4; i++) acc[mt][nt][i] = 0.0f;

    const int nc = Kd / CHUNK;

    auto preload = [&](int c, int s) {
        const int k0 = c * CHUNK;
        const uint32_t abase = sb + (uint32_t)(s * STAGE_HALVES) * 2;
        const uint32_t bbase = abase + (uint32_t)AB_HALVES * 2;
#pragma unroll
        for (int j = 0; j < 4; j++) {
            const int f   = j * 256 + tid;
            const int row = f >> 3;
            const int c8  = f & 7;
            const uint32_t off = (uint32_t)(row * PADH + c8 * 8) * 2;
            cp_async16(abase + off, &A[(size_t)(m0 + row) * lda + k0 + c8 * 8]);
            cp_async16(bbase + off, &B[(size_t)(n0 + row) * ldb + k0 + c8 * 8]);
        }
    };

    preload(0, 0);
    CP_COMMIT();
    if (nc > 1) { preload(1, 1); CP_COMMIT(); }

    int s = 0;
    for (int c = 0; c < nc; c++) {
        if (c + 1 < nc) { CP_WAIT(1); } else { CP_WAIT(0); }
        __syncthreads();
        if (c + 2 < nc) {
            int s2 = s + 2; if (s2 >= NSTAGE) s2 -= NSTAGE;
            preload(c + 2, s2);
            CP_COMMIT();
        }

        const uint32_t stA = sb + (uint32_t)(s * STAGE_HALVES) * 2;
        const uint32_t stB = stA + (uint32_t)AB_HALVES * 2;

#pragma unroll
        for (int kh = 0; kh < CHUNK / 16; kh++) {
            uint32_t af[2][4];
#pragma unroll
            for (int mt = 0; mt < 2; mt++) {
                const int row = wm * 32 + mt * 16 + (lane & 7) + ((lane >> 3) & 1) * 8;
                const int col = kh * 16 + (lane >> 4) * 8;
                LDMX4(af[mt][0], af[mt][1], af[mt][2], af[mt][3],
                      stA + (uint32_t)(row * PADH + col) * 2);
            }
#pragma unroll
            for (int np = 0; np < 4; np++) {
                const int rowb = wn * 64 + np * 16 + (lane >> 4) * 8 + (lane & 7);
                const int colk = kh * 16 + ((lane >> 3) & 1) * 8;
                uint32_t bf[4];
                LDMX4(bf[0], bf[1], bf[2], bf[3],
                      stB + (uint32_t)(rowb * PADH + colk) * 2);
                mma16(acc[0][np * 2    ], af[0], bf + 0);
                mma16(acc[1][np * 2    ], af[1], bf + 0);
                mma16(acc[0][np * 2 + 1], af[0], bf + 2);
                mma16(acc[1][np * 2 + 1], af[1], bf + 2);
            }
        }
        if (++s >= NSTAGE) s -= NSTAGE;
    }
    __syncthreads();

    // ---- epilogue ----
    float* stg = (float*)smemc;                        // 128 x 132 floats
#pragma unroll
    for (int mt = 0; mt < 2; mt++) {
        const int r = wm * 32 + mt * 16 + lq;
#pragma unroll
        for (int nt = 0; nt < 8; nt++) {
            const int cI = wn * 64 + nt * 8 + 2 * lr;
            float v0 = acc[mt][nt][0] * alpha;
            float v1 = acc[mt][nt][1] * alpha;
            float v2 = acc[mt][nt][2] * alpha;
            float v3 = acc[mt][nt][3] * alpha;
            if (EPI == 3) {
                v0 = __expf(v0 - 6.0f); v1 = __expf(v1 - 6.0f);
                v2 = __expf(v2 - 6.0f); v3 = __expf(v3 - 6.0f);
            }
            *(float2*)&stg[(r    ) * 132 + cI] = make_float2(v0, v1);
            *(float2*)&stg[(r + 8) * 132 + cI] = make_float2(v2, v3);
        }
    }
    __syncthreads();

    if (EPI == 3) {
        // per-row partial sums over this block's 128 cols; no C store
        const int row  = tid >> 1;
        const int half = tid & 1;
        float sum = 0.0f;
#pragma unroll
        for (int j4 = 0; j4 < 16; j4++) {
            float4 v = *(const float4*)&stg[row * 132 + half * 64 + j4 * 4];
            sum += v.x + v.y + v.z + v.w;
        }
        sum += __shfl_xor_sync(0xFFFFFFFFu, sum, 1);
        if (half == 0)
            partial[(size_t)(z * 16 + blockIdx.x) * Lc + m0 + row] = sum;
        return;
    }

    float4 bv = make_float4(0.f, 0.f, 0.f, 0.f);
    if (EPI == 1) bv = *(const float4*)&bias[n0 + lane * 4];
#pragma unroll
    for (int it = 0; it < 16; it++) {
        const int r2 = it * 8 + wid;
        float4 v = *(const float4*)&stg[r2 * 132 + lane * 4];
        if (EPI == 1) { v.x += bv.x; v.y += bv.y; v.z += bv.z; v.w += bv.w; }
        if (EPI == 0) {
            *(float4*)&C[(size_t)(m0 + r2) * ldc + n0 + lane * 4] = v;
        } else {
            __half2 h0 = __floats2half2_rn(v.x, v.y);
            __half2 h1 = __floats2half2_rn(v.z, v.w);
            uint2 u;
            u.x = *(uint32_t*)&h0; u.y = *(uint32_t*)&h1;
            *(uint2*)&C[(size_t)(m0 + r2) * ldc + n0 + lane * 4] = u;
        }
    }
}

// ---------------------------------------------------------------------------
// Fused head-sum kernel: for q-tile x k-tile of batch b, recompute per-head
// scores (K=64 chunks = heads), exp, scale by 1/(16*gs), accumulate over heads,
// multiply temporal decay, write unnormalized w (fp32) + row-sum partials.
// 512 thr = 16 warps (4m x 4n), warp tile 32x32.
// ---------------------------------------------------------------------------
static constexpr int OFF_ISH = SMEM_GEMM_BYTES;                 // 2048 floats
static constexpr int SMEM_WSUM_BYTES = OFF_ISH + 2048 * 4;      // 118784

__global__ __launch_bounds__(512, 1)
void wsum_kernel(const __half* __restrict__ qk, const float* __restrict__ gs,
                 const float* __restrict__ td, float* __restrict__ w,
                 float* __restrict__ rnpart)
{
    extern __shared__ __align__(16) char smemc[];
    const uint32_t sb = smem_u32(smemc);
    float* ishs = (float*)(smemc + OFF_ISH);

    const int tid  = threadIdx.x;
    const int wid  = tid >> 5;
    const int lane = tid & 31;
    const int wm   = wid >> 2;          // 0..3
    const int wn   = wid & 3;           // 0..3
    const int lq   = lane >> 2;         // 0..7
    const int lr   = lane & 3;          // 0..3

    const int b  = blockIdx.z;
    const int m0 = blockIdx.y * 128;    // q base
    const int n0 = blockIdx.x * 128;    // k base

    const __half* A = qk + (size_t)b * Lc * 2 * Dc;          // q features
    const __half* B = A + Dc;                                 // k features
    const int ld = 2 * Dc;

    // stage 1/(16*gs) for all 16 heads, this q-tile
#pragma unroll
    for (int j = 0; j < 4; j++) {
        const int idx = j * 512 + tid;           // h*128 + r
        const int h = idx >> 7, r = idx & 127;
        ishs[idx] = 1.0f / (16.0f * gs[(size_t)(b * Hc + h) * Lc + m0 + r]);
    }

    float wacc[2][4][4];
#pragma unroll
    for (int mt = 0; mt < 2; mt++)
#pragma unroll
        for (int nt = 0; nt < 4; nt++)
#pragma unroll
            for (int i = 0; i < 4; i++) wacc[mt][nt][i] = 0.0f;

    auto preload = [&](int c, int s) {
        const int k0 = c * CHUNK;
        const uint32_t abase = sb + (uint32_t)(s * STAGE_HALVES) * 2;
        const uint32_t bbase = abase + (uint32_t)AB_HALVES * 2;
#pragma unroll
        for (int j = 0; j < 2; j++) {
            const int f   = j * 512 + tid;
            const int row = f >> 3;
            const int c8  = f & 7;
            const uint32_t off = (uint32_t)(row * PADH + c8 * 8) * 2;
            cp_async16(abase + off, &A[(size_t)(m0 + row) * ld + k0 + c8 * 8]);
            cp_async16(bbase + off, &B[(size_t)(n0 + row) * ld + k0 + c8 * 8]);
        }
    };

    preload(0, 0);
    CP_COMMIT();
    preload(1, 1);
    CP_COMMIT();

    int s = 0;
    for (int c = 0; c < Hc; c++) {
        if (c + 1 < Hc) { CP_WAIT(1); } else { CP_WAIT(0); }
        __syncthreads();
        if (c + 2 < Hc) {
            int s2 = s + 2; if (s2 >= NSTAGE) s2 -= NSTAGE;
            preload(c + 2, s2);
            CP_COMMIT();
        }

        const uint32_t stA = sb + (uint32_t)(s * STAGE_HALVES) * 2;
        const uint32_t stB = stA + (uint32_t)AB_HALVES * 2;

        float acc[2][4][4];
#pragma unroll
        for (int mt = 0; mt < 2; mt++)
#pragma unroll
            for (int nt = 0; nt < 4; nt++)
#pragma unroll
                for (int i = 0; i < 4; i++) acc[mt][nt][i] = 0.0f;

#pragma unroll
        for (int kh = 0; kh < CHUNK / 16; kh++) {
            uint32_t af[2][4];
#pragma unroll
            for (int mt = 0; mt < 2; mt++) {
                const int row = wm * 32 + mt * 16 + (lane & 7) + ((lane >> 3) & 1) * 8;
                const int col = kh * 16 + (lane >> 4) * 8;
                LDMX4(af[mt][0], af[mt][1], af[mt][2], af[mt][3],
                      stA + (uint32_t)(row * PADH + col) * 2);
            }
#pragma unroll
            for (int np = 0; np < 2; np++) {
                const int rowb = wn * 32 + np * 16 + (lane >> 4) * 8 + (lane & 7);
                const int colk = kh * 16 + ((lane >> 3) & 1) * 8;
                uint32_t bf[4];
                LDMX4(bf[0], bf[1], bf[2], bf[3],
                      stB + (uint32_t)(rowb * PADH + colk) * 2);
                mma16(acc[0][np * 2    ], af[0], bf + 0);
                mma16(acc[1][np * 2    ], af[1], bf + 0);
                mma16(acc[0][np * 2 + 1], af[0], bf + 2);
                mma16(acc[1][np * 2 + 1], af[1], bf + 2);
            }
        }

        // flush: wacc += exp(0.125*acc - 6) * ish[head c][row]
        const float* ish_c = ishs + c * 128;
#pragma unroll
        for (int mt = 0; mt < 2; mt++) {
            const int r = wm * 32 + mt * 16 + lq;
            const float is0 = ish_c[r];
            const float is1 = ish_c[r + 8];
#pragma unroll
            for (int nt = 0; nt < 4; nt++) {
                wacc[mt][nt][0] += __expf(0.125f * acc[mt][nt][0] - 6.0f) * is0;
                wacc[mt][nt][1] += __expf(0.125f * acc[mt][nt][1] - 6.0f) * is0;
                wacc[mt][nt][2] += __expf(0.125f * acc[mt][nt][2] - 6.0f) * is1;
                wacc[mt][nt][3] += __expf(0.125f * acc[mt][nt][3] - 6.0f) * is1;
            }
        }
        if (++s >= NSTAGE) s -= NSTAGE;
    }
    __syncthreads();

    // stage wacc to smem
    float* stg = (float*)smemc;                        // 128 x 132 floats
#pragma unroll
    for (int mt = 0; mt < 2; mt++) {
        const int r = wm * 32 + mt * 16 + lq;
#pragma unroll
        for (int nt = 0; nt < 4; nt++) {
            const int cI = wn * 32 + nt * 8 + 2 * lr;
            *(float2*)&stg[(r    ) * 132 + cI] = make_float2(wacc[mt][nt][0], wacc[mt][nt][1]);
            *(float2*)&stg[(r + 8) * 132 + cI] = make_float2(wacc[mt][nt][2], wacc[mt][nt][3]);
        }
    }
    __syncthreads();

    // decay + row sums + store w (each warp owns full rows -> coalesced)
#pragma unroll
    for (int it = 0; it < 8; it++) {
        const int r2 = it * 16 + wid;
        const size_t rowoff = ((size_t)b * Lc + m0 + r2) * Lc + n0;
        float4 v = *(const float4*)&stg[r2 * 132 + lane * 4];
        const float4 t = *(const float4*)&td[rowoff + lane * 4];
        v.x *= __expf(-0.1f * t.x);
        v.y *= __expf(-0.1f * t.y);
        v.z *= __expf(-0.1f * t.z);
        v.w *= __expf(-0.1f * t.w);
        *(float4*)&w[rowoff + lane * 4] = v;
        float sum = v.x + v.y + v.z + v.w;
#pragma unroll
        for (int o = 16; o; o >>= 1) sum += __shfl_xor_sync(0xFFFFFFFFu, sum, o);
        if (lane == 0)
            rnpart[(size_t)(b * 16 + blockIdx.x) * Lc + m0 + r2] = sum;
    }
}

// ---------------------------------------------------------------------------
__global__ __launch_bounds__(256)
void conv_h_kernel(const float* __restrict__ src, __half* __restrict__ dst)
{
    const size_t i = ((size_t)blockIdx.x * 256 + threadIdx.x) * 8;
    float4 a = *(const float4*)&src[i];
    float4 b = *(const float4*)&src[i + 4];
    __half2 h0 = __floats2half2_rn(a.x, a.y);
    __half2 h1 = __floats2half2_rn(a.z, a.w);
    __half2 h2 = __floats2half2_rn(b.x, b.y);
    __half2 h3 = __floats2half2_rn(b.z, b.w);
    uint4 u;
    u.x = *(uint32_t*)&h0; u.y = *(uint32_t*)&h1;
    u.z = *(uint32_t*)&h2; u.w = *(uint32_t*)&h3;
    *(uint4*)&dst[i] = u;
}

__global__ __launch_bounds__(256)
void transpose_h_kernel(const float* __restrict__ x, __half* __restrict__ xT)
{
    __shared__ float t[32][33];
    const int b  = blockIdx.z;
    const int l0 = blockIdx.y * 32;
    const int d0 = blockIdx.x * 32;
    const int tx = threadIdx.x, ty = threadIdx.y;
#pragma unroll
    for (int j = 0; j < 4; j++)
        t[ty + 8 * j][tx] = x[(size_t)b * Lc * Dc + (size_t)(l0 + ty + 8 * j) * Dc + d0 + tx];
    __syncthreads();
#pragma unroll
    for (int j = 0; j < 4; j++)
        xT[(size_t)b * Dc * Lc + (size_t)(d0 + ty + 8 * j) * Lc + l0 + tx] =
            __float2half_rn(t[tx][ty + 8 * j]);
}

// out[i] = sum over 16 tiles of partials (works for gs and rn layouts)
__global__ __launch_bounds__(256)
void reduce16_kernel(const float* __restrict__ partial, float* __restrict__ outv)
{
    const int i = blockIdx.x * 256 + threadIdx.x;
    const int z = i >> 11, q = i & (Lc - 1);
    float s = 0.0f;
#pragma unroll
    for (int kt = 0; kt < 16; kt++)
        s += partial[(size_t)(z * 16 + kt) * Lc + q];
    outv[i] = s;
}

// attn = w * inv_rn (fp32 + fp16 copies)
__global__ __launch_bounds__(256)
void scale_attn_kernel(const float* __restrict__ w, const float* __restrict__ rn,
                       float* __restrict__ attn, __half* __restrict__ attnH)
{
    const int bq = blockIdx.x;
    const int tid = threadIdx.x;
    const float inv = 1.0f / (rn[bq] + 1e-8f);
    const size_t base = (size_t)bq * Lc;

#pragma unroll
    for (int it = 0; it < 2; it++) {
        const int k = (tid + it * 256) * 4;
        float4 v = *(const float4*)&w[base + k];
        v.x *= inv; v.y *= inv; v.z *= inv; v.w *= inv;
        *(float4*)&attn[base + k] = v;
        __half2 h0 = __floats2half2_rn(v.x, v.y);
        __half2 h1 = __floats2half2_rn(v.z, v.w);
        uint2 u;
        u.x = *(uint32_t*)&h0; u.y = *(uint32_t*)&h1;
        *(uint2*)&attnH[base + k] = u;
    }
}

// ---------------------------------------------------------------------------
extern "C" void kernel_launch(void* const* d_in, const int* in_sizes, int n_in,
                              void* d_out, int out_size)
{
    const float* x    = (const float*)d_in[0];   // [B,L,D]
    const float* td   = (const float*)d_in[1];   // [B,L,L]
    const float* W    = (const float*)d_in[2];   // [3D,D]
    const float* bias = (const float*)d_in[3];   // [3D]
    float* out = (float*)d_out;

    __half *qk, *xh, *Wh, *xTh, *atnH;
    float *wbuf, *part, *gs, *rn, *attn_scratch;
    cudaGetSymbolAddress((void**)&qk, g_qk);
    cudaGetSymbolAddress((void**)&xh, g_xh);
    cudaGetSymbolAddress((void**)&Wh, g_Wh);
    cudaGetSymbolAddress((void**)&xTh, g_xTh);
    cudaGetSymbolAddress((void**)&atnH, g_atnH);
    cudaGetSymbolAddress((void**)&wbuf, g_w);
    cudaGetSymbolAddress((void**)&part, g_part);
    cudaGetSymbolAddress((void**)&gs, g_gs);
    cudaGetSymbolAddress((void**)&rn, g_rn);
    cudaGetSymbolAddress((void**)&attn_scratch, g_attn);

    cudaFuncSetAttribute(gemm_h<0, float>,  cudaFuncAttributeMaxDynamicSharedMemorySize, SMEM_GEMM_BYTES);
    cudaFuncSetAttribute(gemm_h<1, __half>, cudaFuncAttributeMaxDynamicSharedMemorySize, SMEM_GEMM_BYTES);
    cudaFuncSetAttribute(gemm_h<3, __half>, cudaFuncAttributeMaxDynamicSharedMemorySize, SMEM_GEMM_BYTES);
    cudaFuncSetAttribute(wsum_kernel, cudaFuncAttributeMaxDynamicSharedMemorySize, SMEM_WSUM_BYTES);

    const long outElems  = (long)Bc * Lc * Dc;   // 4,194,304
    const long attnElems = (long)Bc * Lc * Lc;   // 8,388,608
    float* out_o = out;
    float* out_a = ((long)out_size >= outElems + attnElems) ? (out + outElems)
                                                            : attn_scratch;

    // Prep: fp16 copies of x, W[:2048]; fp16 x^T
    conv_h_kernel<<<(Bc * Lc * Dc) / 2048, 256>>>(x, xh);
    conv_h_kernel<<<(2 * Dc * Dc) / 2048, 256>>>(W, Wh);
    {
        dim3 grid(Dc / 32, Lc / 32, Bc);
        transpose_h_kernel<<<grid, dim3(32, 8)>>>(x, xTh);
    }

    // K1: qk = fp16(xh @ Wh^T + bias)
    {
        dim3 grid(2 * Dc / 128, (Bc * Lc) / 128, 1);
        gemm_h<1, __half><<<grid, 256, SMEM_GEMM_BYTES>>>(
            xh, Dc, 0, 0,
            Wh, Dc, 0, 0,
            qk, 2 * Dc, 0, 0,
            1, Dc, 1.0f, bias, nullptr);
    }

    // K2a: per-head row sums of exp(scores-6)  (scores NOT stored)
    {
        dim3 grid(Lc / 128, Lc / 128, Bc * Hc);
        gemm_h<3, __half><<<grid, 256, SMEM_GEMM_BYTES>>>(
            qk,       2 * Dc, (long)Lc * 2 * Dc, 64,
            qk + Dc,  2 * Dc, (long)Lc * 2 * Dc, 64,
            (__half*)nullptr, Lc, 0, 0,
            Hc, 64, 0.125f, nullptr, part);
    }
    reduce16_kernel<<<(Bc * Hc * Lc) / 256, 256>>>(part, gs);

    // K2b: recompute scores per head, combine + decay -> w, row-sum partials
    {
        dim3 grid(Lc / 128, Lc / 128, Bc);
        wsum_kernel<<<grid, 512, SMEM_WSUM_BYTES>>>(qk, gs, td, wbuf, part);
    }
    reduce16_kernel<<<(Bc * Lc) / 256, 256>>>(part, rn);

    // attn = w / rn (fp32 output + fp16 for K5)
    scale_attn_kernel<<<Bc * Lc, 256>>>(wbuf, rn, out_a, atnH);

    // K5: output = attnH @ xTh^T
    {
        dim3 grid(Dc / 128, Lc / 128, Bc);
        gemm_h<0, float><<<grid, 256, SMEM_GEMM_BYTES>>>(
            atnH, Lc, (long)Lc * Lc, 0,
            xTh,  Lc, (long)Dc * Lc, 0,
            out_o, Dc, (long)Lc * Dc, 0,
            1, Lc, 1.0f, nullptr, nullptr);
    }
}

// round 8
// speedup vs baseline: 1.1061x; 1.1061x over previous
#include <cuda_runtime.h>
#include <cuda_fp16.h>
#include <cstdint>

// Problem constants
static constexpr int Bc  = 2;
static constexpr int Lc  = 2048;
static constexpr int Dc  = 1024;
static constexpr int Hc  = 16;

// Scratch (__device__ globals: allocation-free rule)
__device__ __half g_qk  [(size_t)Bc * Lc * 2 * Dc];     // [4096][2048] q|k fp16
__device__ __half g_S   [(size_t)Bc * Lc * Hc * Lc];    // exp(score-6) fp16, [b][q][h][k]
__device__ __half g_xh  [(size_t)Bc * Lc * Dc];         // x fp16
__device__ __half g_Wh  [(size_t)2 * Dc * Dc];          // W[:2048] fp16
__device__ __half g_xTh [(size_t)Bc * Dc * Lc];         // x^T fp16
__device__ __half g_atnH[(size_t)Bc * Lc * Lc];         // attn fp16 (K5 operand)
__device__ float  g_part[(size_t)Bc * Hc * 16 * Lc];    // per-ntile row sums
__device__ float  g_gs  [Bc * Hc * Lc];                 // per (b,h,q) sumexp
__device__ float  g_attn[(size_t)Bc * Lc * Lc];         // fallback attn buffer

// ---------------------------------------------------------------------------
__device__ __forceinline__ uint32_t smem_u32(const void* p) {
    uint32_t a;
    asm("{ .reg .u64 t; cvta.to.shared.u64 t, %1; cvt.u32.u64 %0, t; }" : "=r"(a) : "l"(p));
    return a;
}
__device__ __forceinline__ void mma16(float* c, const uint32_t* a, const uint32_t* b) {
    asm volatile(
        "mma.sync.aligned.m16n8k16.row.col.f32.f16.f16.f32 "
        "{%0,%1,%2,%3}, {%4,%5,%6,%7}, {%8,%9}, {%0,%1,%2,%3};"
        : "+f"(c[0]), "+f"(c[1]), "+f"(c[2]), "+f"(c[3])
        : "r"(a[0]), "r"(a[1]), "r"(a[2]), "r"(a[3]), "r"(b[0]), "r"(b[1]));
}
#define LDMX4(r0, r1, r2, r3, addr) \
    asm volatile("ldmatrix.sync.aligned.m8n8.x4.shared.b16 {%0,%1,%2,%3}, [%4];" \
        : "=r"(r0), "=r"(r1), "=r"(r2), "=r"(r3) : "r"(addr))
__device__ __forceinline__ void cp_async16(uint32_t dst, const void* src) {
    asm volatile("cp.async.cg.shared.global [%0], [%1], 16;" :: "r"(dst), "l"(src));
}
#define CP_COMMIT() asm volatile("cp.async.commit_group;" ::: "memory")
#define CP_WAIT(N)  asm volatile("cp.async.wait_group %0;" :: "n"(N) : "memory")

// ---------------------------------------------------------------------------
// fp16 warp-MMA GEMM: C[128x128/blk] = f(alpha * A @ B^T)  (A,B K-major fp16)
// EPI: 0 = fp32 store, 1 = +bias -> fp16, 2 = exp(v-6) -> fp16 + row sums
// 256 thr = 8 warps (4m x 2n), warp tile 32x64, mma m16n8k16, ldmatrix.x4.
// k-chunk 64, 3-stage cp.async ring, ONE barrier per chunk.
// ---------------------------------------------------------------------------
static constexpr int CHUNK = 64;
static constexpr int PADH  = 72;                        // 64 + 8 pad halves
static constexpr int AB_HALVES = 128 * PADH;            // 9216
static constexpr int STAGE_HALVES = 2 * AB_HALVES;      // A then B
static constexpr int NSTAGE = 3;
static constexpr int SMEM_GEMM_BYTES = NSTAGE * STAGE_HALVES * 2;   // 110592

template <int EPI, typename CT>
__global__ __launch_bounds__(256, 2)
void gemm_h(const __half* __restrict__ A, int lda, long aOut, long aIn,
            const __half* __restrict__ B, int ldb, long bOut, long bIn,
            CT* __restrict__ C, int ldc, long cOut, long cIn,
            int zInner, int Kd, float alpha,
            const float* __restrict__ bias, float* __restrict__ partial)
{
    extern __shared__ __align__(16) char smemc[];
    const uint32_t sb = smem_u32(smemc);

    const int tid  = threadIdx.x;
    const int wid  = tid >> 5;
    const int lane = tid & 31;
    const int wm   = wid >> 1;          // 0..3
    const int wn   = wid & 1;           // 0..1
    const int lq   = lane >> 2;         // 0..7
    const int lr   = lane & 3;          // 0..3

    const int z  = blockIdx.z;
    const int zo = z / zInner, zi = z % zInner;
    A += (long)zo * aOut + (long)zi * aIn;
    B += (long)zo * bOut + (long)zi * bIn;
    C += (long)zo * cOut + (long)zi * cIn;

    const int m0 = blockIdx.y * 128;
    const int n0 = blockIdx.x * 128;

    float acc[2][8][4];
#pragma unroll
    for (int mt = 0; mt < 2; mt++)
#pragma unroll
        for (int nt = 0; nt < 8; nt++)
#pragma unroll
            for (int i = 0; i < 4; i++) acc[mt][nt][i] = 0.0f;

    const int nc = Kd / CHUNK;

    auto preload = [&](int c, int s) {
        const int k0 = c * CHUNK;
        const uint32_t abase = sb + (uint32_t)(s * STAGE_HALVES) * 2;
        const uint32_t bbase = abase + (uint32_t)AB_HALVES * 2;
#pragma unroll
        for (int j = 0; j < 4; j++) {
            const int f   = j * 256 + tid;
            const int row = f >> 3;
            const int c8  = f & 7;
            const uint32_t off = (uint32_t)(row * PADH + c8 * 8) * 2;
            cp_async16(abase + off, &A[(size_t)(m0 + row) * lda + k0 + c8 * 8]);
            cp_async16(bbase + off, &B[(size_t)(n0 + row) * ldb + k0 + c8 * 8]);
        }
    };

    preload(0, 0);
    CP_COMMIT();
    if (nc > 1) { preload(1, 1); CP_COMMIT(); }

    int s = 0;
    for (int c = 0; c < nc; c++) {
        if (c + 1 < nc) { CP_WAIT(1); } else { CP_WAIT(0); }
        __syncthreads();
        if (c + 2 < nc) {
            int s2 = s + 2; if (s2 >= NSTAGE) s2 -= NSTAGE;
            preload(c + 2, s2);
            CP_COMMIT();
        }

        const uint32_t stA = sb + (uint32_t)(s * STAGE_HALVES) * 2;
        const uint32_t stB = stA + (uint32_t)AB_HALVES * 2;

#pragma unroll
        for (int kh = 0; kh < CHUNK / 16; kh++) {
            uint32_t af[2][4];
#pragma unroll
            for (int mt = 0; mt < 2; mt++) {
                const int row = wm * 32 + mt * 16 + (lane & 7) + ((lane >> 3) & 1) * 8;
                const int col = kh * 16 + (lane >> 4) * 8;
                LDMX4(af[mt][0], af[mt][1], af[mt][2], af[mt][3],
                      stA + (uint32_t)(row * PADH + col) * 2);
            }
#pragma unroll
            for (int np = 0; np < 4; np++) {
                const int rowb = wn * 64 + np * 16 + (lane >> 4) * 8 + (lane & 7);
                const int colk = kh * 16 + ((lane >> 3) & 1) * 8;
                uint32_t bf[4];
                LDMX4(bf[0], bf[1], bf[2], bf[3],
                      stB + (uint32_t)(rowb * PADH + colk) * 2);
                mma16(acc[0][np * 2    ], af[0], bf + 0);
                mma16(acc[1][np * 2    ], af[1], bf + 0);
                mma16(acc[0][np * 2 + 1], af[0], bf + 2);
                mma16(acc[1][np * 2 + 1], af[1], bf + 2);
            }
        }
        if (++s >= NSTAGE) s -= NSTAGE;
    }
    __syncthreads();

    // ---- epilogue: regs -> fp32 staged smem -> coalesced GMEM ----
    float* stg = (float*)smemc;                        // 128 x 132 floats
#pragma unroll
    for (int mt = 0; mt < 2; mt++) {
        const int r = wm * 32 + mt * 16 + lq;
#pragma unroll
        for (int nt = 0; nt < 8; nt++) {
            const int cI = wn * 64 + nt * 8 + 2 * lr;
            float v0 = acc[mt][nt][0] * alpha;
            float v1 = acc[mt][nt][1] * alpha;
            float v2 = acc[mt][nt][2] * alpha;
            float v3 = acc[mt][nt][3] * alpha;
            if (EPI == 2) {
                v0 = __expf(v0 - 6.0f); v1 = __expf(v1 - 6.0f);
                v2 = __expf(v2 - 6.0f); v3 = __expf(v3 - 6.0f);
            }
            *(float2*)&stg[(r    ) * 132 + cI] = make_float2(v0, v1);
            *(float2*)&stg[(r + 8) * 132 + cI] = make_float2(v2, v3);
        }
    }
    __syncthreads();

    if (EPI == 2) {
        const int row  = tid >> 1;
        const int half = tid & 1;
        float sum = 0.0f;
#pragma unroll
        for (int j4 = 0; j4 < 16; j4++) {
            float4 v = *(const float4*)&stg[row * 132 + half * 64 + j4 * 4];
            sum += v.x + v.y + v.z + v.w;
        }
        sum += __shfl_xor_sync(0xFFFFFFFFu, sum, 1);
        if (half == 0)
            partial[(size_t)(z * 16 + blockIdx.x) * Lc + m0 + row] = sum;
    }

    float4 bv = make_float4(0.f, 0.f, 0.f, 0.f);
    if (EPI == 1) bv = *(const float4*)&bias[n0 + lane * 4];
#pragma unroll
    for (int it = 0; it < 16; it++) {
        const int r2 = it * 8 + wid;
        float4 v = *(const float4*)&stg[r2 * 132 + lane * 4];
        if (EPI == 1) { v.x += bv.x; v.y += bv.y; v.z += bv.z; v.w += bv.w; }
        if (EPI == 0) {
            *(float4*)&C[(size_t)(m0 + r2) * ldc + n0 + lane * 4] = v;
        } else {
            __half2 h0 = __floats2half2_rn(v.x, v.y);
            __half2 h1 = __floats2half2_rn(v.z, v.w);
            uint2 u;
            u.x = *(uint32_t*)&h0; u.y = *(uint32_t*)&h1;
            *(uint2*)&C[(size_t)(m0 + r2) * ldc + n0 + lane * 4] = u;
        }
    }
}

// ---------------------------------------------------------------------------
__global__ __launch_bounds__(256)
void conv_h_kernel(const float* __restrict__ src, __half* __restrict__ dst)
{
    const size_t i = ((size_t)blockIdx.x * 256 + threadIdx.x) * 8;
    float4 a = *(const float4*)&src[i];
    float4 b = *(const float4*)&src[i + 4];
    __half2 h0 = __floats2half2_rn(a.x, a.y);
    __half2 h1 = __floats2half2_rn(a.z, a.w);
    __half2 h2 = __floats2half2_rn(b.x, b.y);
    __half2 h3 = __floats2half2_rn(b.z, b.w);
    uint4 u;
    u.x = *(uint32_t*)&h0; u.y = *(uint32_t*)&h1;
    u.z = *(uint32_t*)&h2; u.w = *(uint32_t*)&h3;
    *(uint4*)&dst[i] = u;
}

// x [B,L,D] -> xT [B,D,L] fp16
__global__ __launch_bounds__(256)
void transpose_h_kernel(const float* __restrict__ x, __half* __restrict__ xT)
{
    __shared__ float t[32][33];
    const int b  = blockIdx.z;
    const int l0 = blockIdx.y * 32;
    const int d0 = blockIdx.x * 32;
    const int tx = threadIdx.x, ty = threadIdx.y;
#pragma unroll
    for (int j = 0; j < 4; j++)
        t[ty + 8 * j][tx] = x[(size_t)b * Lc * Dc + (size_t)(l0 + ty + 8 * j) * Dc + d0 + tx];
    __syncthreads();
#pragma unroll
    for (int j = 0; j < 4; j++)
        xT[(size_t)b * Dc * Lc + (size_t)(d0 + ty + 8 * j) * Lc + l0 + tx] =
            __float2half_rn(t[tx][ty + 8 * j]);
}

// gs[z][q] = sum over 16 n-tiles of partials
__global__ __launch_bounds__(256)
void reduce_gs_kernel(const float* __restrict__ partial, float* __restrict__ gs)
{
    const int i = blockIdx.x * 256 + threadIdx.x;
    const int z = i >> 11, q = i & (Lc - 1);
    float s = 0.0f;
#pragma unroll
    for (int kt = 0; kt < 16; kt++)
        s += partial[(size_t)(z * 16 + kt) * Lc + q];
    gs[i] = s;
}

// ---------------------------------------------------------------------------
// Per (b,q): head-mean of exp-scores (fp16, [b][q][h][k] CONTIGUOUS 64KB/row),
// temporal decay, renormalize. Writes fp32 attn (output) + fp16 (K5 operand).
// ---------------------------------------------------------------------------
__global__ __launch_bounds__(256)
void attn_kernel(const __half* __restrict__ E, const float* __restrict__ gs,
                 const float* __restrict__ td, float* __restrict__ attn,
                 __half* __restrict__ attnH)
{
    const int bq = blockIdx.x;            // 0..4095
    const int b  = bq >> 11;
    const int q  = bq & (Lc - 1);
    const int tid = threadIdx.x;

    __shared__ float ish[Hc];
    __shared__ float red[8];

    if (tid < Hc)
        ish[tid] = 1.0f / (16.0f * gs[(b * Hc + tid) * Lc + q]);
    __syncthreads();

    // this (b,q)'s S block: 16 heads x 2048 halves, contiguous
    const __half* Eq = E + (size_t)bq * Hc * Lc;

    float acc[8];
#pragma unroll
    for (int j = 0; j < 8; j++) acc[j] = 0.0f;

#pragma unroll
    for (int h = 0; h < Hc; h++) {
        const uint4 u = *(const uint4*)&Eq[(size_t)h * Lc + 8 * tid];
        const float is = ish[h];
        float2 f0 = __half22float2(*(const __half2*)&u.x);
        float2 f1 = __half22float2(*(const __half2*)&u.y);
        float2 f2 = __half22float2(*(const __half2*)&u.z);
        float2 f3 = __half22float2(*(const __half2*)&u.w);
        acc[0] += f0.x * is; acc[1] += f0.y * is;
        acc[2] += f1.x * is; acc[3] += f1.y * is;
        acc[4] += f2.x * is; acc[5] += f2.y * is;
        acc[6] += f3.x * is; acc[7] += f3.y * is;
    }

    const float4 t0 = *(const float4*)&td[(size_t)bq * Lc + 8 * tid];
    const float4 t1 = *(const float4*)&td[(size_t)bq * Lc + 8 * tid + 4];
    float w[8];
    w[0] = acc[0] * __expf(-0.1f * t0.x);
    w[1] = acc[1] * __expf(-0.1f * t0.y);
    w[2] = acc[2] * __expf(-0.1f * t0.z);
    w[3] = acc[3] * __expf(-0.1f * t0.w);
    w[4] = acc[4] * __expf(-0.1f * t1.x);
    w[5] = acc[5] * __expf(-0.1f * t1.y);
    w[6] = acc[6] * __expf(-0.1f * t1.z);
    w[7] = acc[7] * __expf(-0.1f * t1.w);

    float lsum = 0.0f;
#pragma unroll
    for (int j = 0; j < 8; j++) lsum += w[j];
#pragma unroll
    for (int o = 16; o; o >>= 1) lsum += __shfl_xor_sync(0xFFFFFFFFu, lsum, o);
    if ((tid & 31) == 0) red[tid >> 5] = lsum;
    __syncthreads();
    if (tid == 0) {
        float t = 0.0f;
#pragma unroll
        for (int i = 0; i < 8; i++) t += red[i];
        red[0] = 1.0f / (t + 1e-8f);
    }
    __syncthreads();
    const float inv = red[0];

    float o[8];
#pragma unroll
    for (int j = 0; j < 8; j++) o[j] = w[j] * inv;
    *(float4*)&attn[(size_t)bq * Lc + 8 * tid]     = make_float4(o[0], o[1], o[2], o[3]);
    *(float4*)&attn[(size_t)bq * Lc + 8 * tid + 4] = make_float4(o[4], o[5], o[6], o[7]);

    __half2 h0 = __floats2half2_rn(o[0], o[1]);
    __half2 h1 = __floats2half2_rn(o[2], o[3]);
    __half2 h2 = __floats2half2_rn(o[4], o[5]);
    __half2 h3 = __floats2half2_rn(o[6], o[7]);
    uint4 u;
    u.x = *(uint32_t*)&h0; u.y = *(uint32_t*)&h1;
    u.z = *(uint32_t*)&h2; u.w = *(uint32_t*)&h3;
    *(uint4*)&attnH[(size_t)bq * Lc + 8 * tid] = u;
}

// ---------------------------------------------------------------------------
extern "C" void kernel_launch(void* const* d_in, const int* in_sizes, int n_in,
                              void* d_out, int out_size)
{
    const float* x    = (const float*)d_in[0];   // [B,L,D]
    const float* td   = (const float*)d_in[1];   // [B,L,L]
    const float* W    = (const float*)d_in[2];   // [3D,D]
    const float* bias = (const float*)d_in[3];   // [3D]
    float* out = (float*)d_out;

    __half *qk, *S, *xh, *Wh, *xTh, *atnH;
    float *part, *gs, *attn_scratch;
    cudaGetSymbolAddress((void**)&qk, g_qk);
    cudaGetSymbolAddress((void**)&S, g_S);
    cudaGetSymbolAddress((void**)&xh, g_xh);
    cudaGetSymbolAddress((void**)&Wh, g_Wh);
    cudaGetSymbolAddress((void**)&xTh, g_xTh);
    cudaGetSymbolAddress((void**)&atnH, g_atnH);
    cudaGetSymbolAddress((void**)&part, g_part);
    cudaGetSymbolAddress((void**)&gs, g_gs);
    cudaGetSymbolAddress((void**)&attn_scratch, g_attn);

    cudaFuncSetAttribute(gemm_h<0, float>,  cudaFuncAttributeMaxDynamicSharedMemorySize, SMEM_GEMM_BYTES);
    cudaFuncSetAttribute(gemm_h<1, __half>, cudaFuncAttributeMaxDynamicSharedMemorySize, SMEM_GEMM_BYTES);
    cudaFuncSetAttribute(gemm_h<2, __half>, cudaFuncAttributeMaxDynamicSharedMemorySize, SMEM_GEMM_BYTES);

    const long outElems  = (long)Bc * Lc * Dc;   // 4,194,304
    const long attnElems = (long)Bc * Lc * Lc;   // 8,388,608
    float* out_o = out;
    float* out_a = ((long)out_size >= outElems + attnElems) ? (out + outElems)
                                                            : attn_scratch;

    // Prep: fp16 copies of x, W[:2048]; fp16 x^T
    conv_h_kernel<<<(Bc * Lc * Dc) / 2048, 256>>>(x, xh);
    conv_h_kernel<<<(2 * Dc * Dc) / 2048, 256>>>(W, Wh);
    {
        dim3 grid(Dc / 32, Lc / 32, Bc);
        transpose_h_kernel<<<grid, dim3(32, 8)>>>(x, xTh);
    }

    // K1: qk = fp16(xh @ Wh^T + bias)
    {
        dim3 grid(2 * Dc / 128, (Bc * Lc) / 128, 1);
        gemm_h<1, __half><<<grid, 256, SMEM_GEMM_BYTES>>>(
            xh, Dc, 0, 0,
            Wh, Dc, 0, 0,
            qk, 2 * Dc, 0, 0,
            1, Dc, 1.0f, bias, nullptr);
    }

    // K2: S[b][q][h][k] = fp16(exp(0.125*Q@K^T - 6)) — interleaved layout:
    //     ldc = H*L (row stride over q), cOut = L*H*L (batch), cIn = L (head)
    {
        dim3 grid(Lc / 128, Lc / 128, Bc * Hc);
        gemm_h<2, __half><<<grid, 256, SMEM_GEMM_BYTES>>>(
            qk,       2 * Dc, (long)Lc * 2 * Dc, 64,
            qk + Dc,  2 * Dc, (long)Lc * 2 * Dc, 64,
            S,        Hc * Lc, (long)Lc * Hc * Lc, (long)Lc,
            Hc, 64, 0.125f, nullptr, part);
    }

    // K3: gs = sum of partials
    reduce_gs_kernel<<<(Bc * Hc * Lc) / 256, 256>>>(part, gs);

    // K4: head-mean + decay + renormalize -> attn fp32 + fp16 (contiguous S reads)
    attn_kernel<<<Bc * Lc, 256>>>(S, gs, td, out_a, atnH);

    // K5: output = attnH @ xTh^T
    {
        dim3 grid(Dc / 128, Lc / 128, Bc);
        gemm_h<0, float><<<grid, 256, SMEM_GEMM_BYTES>>>(
            atnH, Lc, (long)Lc * Lc, 0,
            xTh,  Lc, (long)Dc * Lc, 0,
            out_o, Dc, (long)Lc * Dc, 0,
            1, Lc, 1.0f, nullptr, nullptr);
    }
}